// round 14
// baseline (speedup 1.0000x reference)
#include <cuda_runtime.h>
#include <cuda_bf16.h>
#include <math.h>

#define N_NODES 50000
#define N_EDGES 200000

typedef unsigned long long u64;

// ---- packed fp32x2 helpers ----
__device__ __forceinline__ u64 pk2(float x, float y) {
    u64 r; asm("mov.b64 %0,{%1,%2};" : "=l"(r) : "f"(x), "f"(y)); return r;
}
__device__ __forceinline__ void fma2(u64& d, u64 a, u64 b) {
    asm("fma.rn.f32x2 %0,%1,%2,%0;" : "+l"(d) : "l"(a), "l"(b));
}
__device__ __forceinline__ float2 up2(u64 v) {
    float2 r; asm("mov.b64 {%0,%1},%2;" : "=f"(r.x), "=f"(r.y) : "l"(v)); return r;
}
__device__ __forceinline__ unsigned pkbf(float lo, float hi) {
    unsigned r; asm("cvt.rn.bf16x2.f32 %0,%1,%2;" : "=r"(r) : "f"(hi), "f"(lo)); return r;
}
__device__ __forceinline__ float2 b22f(unsigned u) {
    __nv_bfloat162 h = *reinterpret_cast<__nv_bfloat162*>(&u);
    return __bfloat1622float2(h);
}

// ---------------- scratch ----------------
__device__ float g_M[256 * 256];
__device__ float g_bcomb[256];
__device__ float g_weff[128];
__device__ float g_hid[(size_t)N_NODES * 256];
__device__ __nv_bfloat16 g_ysb[(size_t)N_NODES * 256];
__device__ __nv_bfloat16 g_zvb[(size_t)N_NODES * 384];
__device__ __nv_bfloat16 g_hb[(size_t)N_NODES * 640];
__device__ float g_tp[N_EDGES];

// ---------------- stream/event resources ----------
struct AsyncRes {
    cudaStream_t s1;
    cudaEvent_t eNG, eA;
    AsyncRes() {
        cudaStreamCreateWithFlags(&s1, cudaStreamNonBlocking);
        cudaEventCreateWithFlags(&eNG, cudaEventDisableTiming);
        cudaEventCreateWithFlags(&eA, cudaEventDisableTiming);
    }
};
static AsyncRes g_ar;

// ---------------- prep ----------------
__global__ void prep_kernel(const float* __restrict__ A1, const float* __restrict__ Ws,
                            const float* __restrict__ Wsb, const float* __restrict__ ab1,
                            const float* __restrict__ Wcoord, const float* __restrict__ Wv) {
    if (blockIdx.x == 256) {
        int c = threadIdx.x;
        if (c < 128) {
            float acc = 0.f;
#pragma unroll 8
            for (int d = 0; d < 128; d++) acc = fmaf(Wcoord[d], Wv[d * 128 + c], acc);
            g_weff[c] = acc;
        }
        return;
    }
    __shared__ float a1s[256];
    int i = blockIdx.x, j = threadIdx.x;
    a1s[j] = A1[i * 256 + j];
    __syncthreads();
    float a[8];
#pragma unroll
    for (int u = 0; u < 8; u++) a[u] = 0.f;
#pragma unroll 4
    for (int k = 0; k < 256; k += 8) {
#pragma unroll
        for (int u = 0; u < 8; u++)
            a[u] = fmaf(a1s[k + u], Ws[(k + u) * 256 + j], a[u]);
    }
    g_M[i * 256 + j] = ((a[0] + a[1]) + (a[2] + a[3])) + ((a[4] + a[5]) + (a[6] + a[7]));
    if (j == 0) {
        float b = ab1[i];
        for (int k = 0; k < 256; k++) b = fmaf(a1s[k], Wsb[k], b);
        g_bcomb[i] = b;
    }
}

// ---------------- node GEMM (R10-proven) ----------------
#define NG_STR 132
__global__ __launch_bounds__(256) void node_gemm(const float* __restrict__ h,
                                                 const float* __restrict__ Wtp00) {
    __shared__ float As[16 * NG_STR];
    __shared__ float Bs[16 * NG_STR];
    const int t = threadIdx.x;
    const int n0 = blockIdx.x * 128;
    const int by = blockIdx.y;
    const float* Bbase = (by < 2) ? (g_M + (size_t)by * 128 * 256)
                                  : (Wtp00 + (size_t)(by - 2) * 128 * 256);
    const int lr = t >> 1;
    const int lk = (t & 1) * 8;
    const int ty = t >> 4, tx = t & 15;
    const int anode = n0 + lr;
    const bool aval = anode < N_NODES;
    const float* Aptr = h + (size_t)anode * 640 + lk;
    const float* Bptr = Bbase + (size_t)lr * 256 + lk;

    u64 acc[8][4];
#pragma unroll
    for (int m = 0; m < 8; m++)
#pragma unroll
        for (int q = 0; q < 4; q++) acc[m][q] = 0ull;

    float4 pa0, pa1, pb0, pb1;
    const float4 z4 = make_float4(0.f, 0.f, 0.f, 0.f);
    pa0 = aval ? *(const float4*)(Aptr + 0) : z4;
    pa1 = aval ? *(const float4*)(Aptr + 4) : z4;
    pb0 = *(const float4*)(Bptr + 0);
    pb1 = *(const float4*)(Bptr + 4);

    const u64* B64 = (const u64*)Bs;
    for (int k0 = 0; k0 < 256; k0 += 16) {
        if (by == 0 && aval) {
            uint4 o = make_uint4(pkbf(pa0.x, pa0.y), pkbf(pa0.z, pa0.w),
                                 pkbf(pa1.x, pa1.y), pkbf(pa1.z, pa1.w));
            *(uint4*)&g_hb[(size_t)anode * 640 + k0 + lk] = o;
        }
        As[(lk + 0) * NG_STR + lr] = pa0.x;
        As[(lk + 1) * NG_STR + lr] = pa0.y;
        As[(lk + 2) * NG_STR + lr] = pa0.z;
        As[(lk + 3) * NG_STR + lr] = pa0.w;
        As[(lk + 4) * NG_STR + lr] = pa1.x;
        As[(lk + 5) * NG_STR + lr] = pa1.y;
        As[(lk + 6) * NG_STR + lr] = pa1.z;
        As[(lk + 7) * NG_STR + lr] = pa1.w;
        Bs[(lk + 0) * NG_STR + lr] = pb0.x;
        Bs[(lk + 1) * NG_STR + lr] = pb0.y;
        Bs[(lk + 2) * NG_STR + lr] = pb0.z;
        Bs[(lk + 3) * NG_STR + lr] = pb0.w;
        Bs[(lk + 4) * NG_STR + lr] = pb1.x;
        Bs[(lk + 5) * NG_STR + lr] = pb1.y;
        Bs[(lk + 6) * NG_STR + lr] = pb1.z;
        Bs[(lk + 7) * NG_STR + lr] = pb1.w;
        __syncthreads();
        if (k0 + 16 < 256) {
            pa0 = aval ? *(const float4*)(Aptr + k0 + 16) : z4;
            pa1 = aval ? *(const float4*)(Aptr + k0 + 20) : z4;
            pb0 = *(const float4*)(Bptr + k0 + 16);
            pb1 = *(const float4*)(Bptr + k0 + 20);
        }
#pragma unroll
        for (int kk = 0; kk < 16; kk++) {
            float4 a0 = *(const float4*)&As[kk * NG_STR + ty * 8];
            float4 a1 = *(const float4*)&As[kk * NG_STR + ty * 8 + 4];
            u64 b0 = B64[kk * 66 + tx * 2];
            u64 b1 = B64[kk * 66 + tx * 2 + 1];
            u64 b2 = B64[kk * 66 + 32 + tx * 2];
            u64 b3 = B64[kk * 66 + 33 + tx * 2];
            float av[8] = {a0.x, a0.y, a0.z, a0.w, a1.x, a1.y, a1.z, a1.w};
#pragma unroll
            for (int m = 0; m < 8; m++) {
                u64 aa = pk2(av[m], av[m]);
                fma2(acc[m][0], aa, b0);
                fma2(acc[m][1], aa, b1);
                fma2(acc[m][2], aa, b2);
                fma2(acc[m][3], aa, b3);
            }
        }
        __syncthreads();
    }

    const bool isHid = (by < 2);
    const int half = (by & 1) * 128;
    const int j0 = half + tx * 4;
    const int j1 = half + 64 + tx * 4;
#pragma unroll
    for (int m = 0; m < 8; m++) {
        int node = n0 + ty * 8 + m;
        if (node >= N_NODES) continue;
        float2 v0 = up2(acc[m][0]), v1 = up2(acc[m][1]);
        float2 v2 = up2(acc[m][2]), v3 = up2(acc[m][3]);
        if (isHid) {
            float4 bc0 = *(const float4*)&g_bcomb[j0];
            float4 bc1 = *(const float4*)&g_bcomb[j1];
            float x0 = v0.x + bc0.x, x1 = v0.y + bc0.y, x2 = v1.x + bc0.z, x3 = v1.y + bc0.w;
            float y0 = v2.x + bc1.x, y1 = v2.y + bc1.y, y2 = v3.x + bc1.z, y3 = v3.y + bc1.w;
            float4 o0 = make_float4(x0 / (1.f + __expf(-x0)), x1 / (1.f + __expf(-x1)),
                                    x2 / (1.f + __expf(-x2)), x3 / (1.f + __expf(-x3)));
            float4 o1 = make_float4(y0 / (1.f + __expf(-y0)), y1 / (1.f + __expf(-y1)),
                                    y2 / (1.f + __expf(-y2)), y3 / (1.f + __expf(-y3)));
            *(float4*)&g_hid[(size_t)node * 256 + j0] = o0;
            *(float4*)&g_hid[(size_t)node * 256 + j1] = o1;
        } else {
            uint2 o0 = make_uint2(pkbf(v0.x, v0.y), pkbf(v1.x, v1.y));
            uint2 o1 = make_uint2(pkbf(v2.x, v2.y), pkbf(v3.x, v3.y));
            *(uint2*)&g_ysb[(size_t)node * 256 + j0] = o0;
            *(uint2*)&g_ysb[(size_t)node * 256 + j1] = o1;
        }
    }
}

// ---------------- zv: c-split (R10-proven) ----------------
#define ZVN 32
#define ZV_RST 98
#define ZV_BST 66
#define ZT_STR 196
__global__ __launch_bounds__(256, 3) void zv_kernel(const float* __restrict__ h,
                                                    const float* __restrict__ Wtp11,
                                                    float* __restrict__ out_r0) {
    extern __shared__ float sm[];
    float* vsT = sm;
    float* Bs = sm + 128 * ZV_RST;
    float* weffs = Bs + 32 * ZV_BST;
    const int t = threadIdx.x;
    const int n0 = blockIdx.x * ZVN;
    const int c_base = blockIdx.y * 64;

#pragma unroll
    for (int q = 0; q < 12; q++) {
        int fidx = t + 256 * q;
        int n = fidx / 96, j4 = (fidx % 96) * 4;
        float4 v = (n0 + n < N_NODES)
                       ? *(const float4*)&h[(size_t)(n0 + n) * 640 + 256 + j4]
                       : make_float4(0.f, 0.f, 0.f, 0.f);
        if (blockIdx.y == 0 && n0 + n < N_NODES) {
            uint2 o = make_uint2(pkbf(v.x, v.y), pkbf(v.z, v.w));
            *(uint2*)&g_hb[(size_t)(n0 + n) * 640 + 256 + j4] = o;
        }
        float vv[4] = {v.x, v.y, v.z, v.w};
#pragma unroll
        for (int s = 0; s < 4; s++) {
            int j = j4 + s;
            vsT[(j / 3) * ZV_RST + n * 3 + (j % 3)] = vv[s];
        }
    }
    if (blockIdx.y == 0 && t < 128) weffs[t] = g_weff[t];
    __syncthreads();

    if (blockIdx.y == 0 && t < 96) {
        int n = t / 3, i = t % 3;
        if (n0 + n < N_NODES) {
            float acc = 0.f;
#pragma unroll 8
            for (int d = 0; d < 128; d++) acc = fmaf(vsT[d * ZV_RST + t], weffs[d], acc);
            out_r0[(size_t)(n0 + n) * 3 + i] = acc;
        }
    }

    const int ty = t >> 4, tx = t & 15;
    u64 acc[6][2];
#pragma unroll
    for (int j = 0; j < 6; j++) { acc[j][0] = 0ull; acc[j][1] = 0ull; }

    const u64* B64 = (const u64*)Bs;
    const u64* V64 = (const u64*)vsT;
    for (int chn = 0; chn < 4; chn++) {
        if (chn) __syncthreads();
        int d0 = chn * 32;
#pragma unroll
        for (int q = 0; q < 2; q++) {
            int fidx = t + 256 * q;
            int cc = fidx >> 3, d4 = (fidx & 7) * 4;
            float4 w = *(const float4*)&Wtp11[(size_t)(c_base + cc) * 128 + d0 + d4];
            Bs[(d4 + 0) * ZV_BST + cc] = w.x;
            Bs[(d4 + 1) * ZV_BST + cc] = w.y;
            Bs[(d4 + 2) * ZV_BST + cc] = w.z;
            Bs[(d4 + 3) * ZV_BST + cc] = w.w;
        }
        __syncthreads();
#pragma unroll 4
        for (int dd = 0; dd < 32; dd++) {
            int d = d0 + dd;
            u64 a01 = V64[d * 49 + ty * 3];
            u64 a23 = V64[d * 49 + ty * 3 + 1];
            u64 a45 = V64[d * 49 + ty * 3 + 2];
            u64 b0 = B64[dd * 33 + tx * 2];
            u64 b1 = B64[dd * 33 + tx * 2 + 1];
            float2 f01 = up2(a01), f23 = up2(a23), f45 = up2(a45);
            float av[6] = {f01.x, f01.y, f23.x, f23.y, f45.x, f45.y};
#pragma unroll
            for (int j = 0; j < 6; j++) {
                u64 aa = pk2(av[j], av[j]);
                fma2(acc[j][0], aa, b0);
                fma2(acc[j][1], aa, b1);
            }
        }
    }

    __syncthreads();
    float* zt = vsT;
#pragma unroll
    for (int j = 0; j < 6; j++) {
        int r = ty * 6 + j;
        int n = r / 3, i = r % 3;
        float2 v0 = up2(acc[j][0]);
        float2 v1 = up2(acc[j][1]);
        int cp = tx * 4;
        zt[n * ZT_STR + (cp + 0) * 3 + i] = v0.x;
        zt[n * ZT_STR + (cp + 1) * 3 + i] = v0.y;
        zt[n * ZT_STR + (cp + 2) * 3 + i] = v1.x;
        zt[n * ZT_STR + (cp + 3) * 3 + i] = v1.y;
    }
    __syncthreads();
#pragma unroll
    for (int q = 0; q < 6; q++) {
        int fidx = t + 256 * q;
        int n = fidx / 48, w = fidx % 48;
        if (n0 + n < N_NODES) {
            float4 v = *(const float4*)&zt[n * ZT_STR + w * 4];
            uint2 o = make_uint2(pkbf(v.x, v.y), pkbf(v.z, v.w));
            *(uint2*)&g_zvb[(size_t)(n0 + n) * 384 + c_base * 3 + w * 4] = o;
        }
    }
}

// ---------------- atom logits (R10-proven) ----------------
#define AT_N 64
__global__ __launch_bounds__(256) void atom_kernel(float* __restrict__ out,
                                                   const float* __restrict__ A2,
                                                   const float* __restrict__ b2) {
    extern __shared__ float sma[];
    float* hs = sma;
    float* a2s = hs + AT_N * 258;
    float* b2s = a2s + 16 * 258;
    const int t = threadIdx.x;
    const int n0 = blockIdx.x * AT_N;

#pragma unroll
    for (int q = 0; q < 32; q++) {
        int idx = t + 256 * q;
        int n = idx >> 7, k2 = (idx & 127) * 2;
        float2 v = (n0 + n < N_NODES)
                       ? *(const float2*)&g_hid[(size_t)(n0 + n) * 256 + k2]
                       : make_float2(0.f, 0.f);
        *(float2*)&hs[n * 258 + k2] = v;
    }
#pragma unroll
    for (int q = 0; q < 8; q++) {
        int idx = t + 256 * q;
        int j = idx >> 7, k2 = (idx & 127) * 2;
        *(float2*)&a2s[j * 258 + k2] = *(const float2*)&A2[j * 256 + k2];
    }
    if (t < 16) b2s[t] = b2[t];
    __syncthreads();

    const int jp = t & 7;
    const int np = t >> 3;
    const u64* H0 = (const u64*)hs + (2 * np) * 129;
    const u64* H1 = H0 + 129;
    const u64* A0 = (const u64*)a2s + (2 * jp) * 129;
    const u64* A1 = A0 + 129;
    u64 c00 = 0ull, c01 = 0ull, c10 = 0ull, c11 = 0ull;
#pragma unroll 8
    for (int kk = 0; kk < 128; kk++) {
        u64 h0 = H0[kk], h1 = H1[kk];
        u64 a0 = A0[kk], a1 = A1[kk];
        fma2(c00, h0, a0);
        fma2(c01, h0, a1);
        fma2(c10, h1, a0);
        fma2(c11, h1, a1);
    }
    float2 r00 = up2(c00), r01 = up2(c01), r10 = up2(c10), r11 = up2(c11);
    int n = n0 + 2 * np, j = 2 * jp;
    float bj0 = b2s[j], bj1 = b2s[j + 1];
    if (n < N_NODES) {
        *(float2*)&out[(size_t)n * 16 + j] =
            make_float2(r00.x + r00.y + bj0, r01.x + r01.y + bj1);
    }
    if (n + 1 < N_NODES) {
        *(float2*)&out[(size_t)(n + 1) * 16 + j] =
            make_float2(r10.x + r10.y + bj0, r11.x + r11.y + bj1);
    }
}

// ---------------- tp (R10-proven) ----------------
__global__ __launch_bounds__(256) void tp_kernel(const int* __restrict__ ei) {
    const int w = threadIdx.x >> 5, l = threadIdx.x & 31;
    const int e = blockIdx.x * 8 + w;
    const int row = ei[e];
    const int col = ei[N_EDGES + e];
    const __nv_bfloat16* hb = g_hb + (size_t)row * 640;
    const uint4* ys4 = (const uint4*)(g_ysb + (size_t)col * 256);
    const uint2* zv2 = (const uint2*)(g_zvb + (size_t)col * 384);
    const uint2* hv2 = (const uint2*)(hb + 256);

    uint4 x = *(const uint4*)(hb + 8 * l);
    uint4 y = ys4[l];
    float2 xa = b22f(x.x), xb = b22f(x.y), xc = b22f(x.z), xd = b22f(x.w);
    float2 ya = b22f(y.x), yb = b22f(y.y), yc = b22f(y.z), yd = b22f(y.w);
    float ss = xa.x * ya.x + xa.y * ya.y + xb.x * yb.x + xb.y * yb.y +
               xc.x * yc.x + xc.y * yc.y + xd.x * yd.x + xd.y * yd.y;

    float vv = 0.f;
#pragma unroll
    for (int q = 0; q < 3; q++) {
        uint2 xv = hv2[3 * l + q];
        uint2 z = zv2[3 * l + q];
        float2 x0 = b22f(xv.x), x1 = b22f(xv.y);
        float2 z0 = b22f(z.x), z1 = b22f(z.y);
        vv = fmaf(x0.x, z0.x, vv);
        vv = fmaf(x0.y, z0.y, vv);
        vv = fmaf(x1.x, z1.x, vv);
        vv = fmaf(x1.y, z1.y, vv);
    }
    float val = fmaf(vv, 0.57735026919f, ss);
#pragma unroll
    for (int off = 16; off; off >>= 1) val += __shfl_xor_sync(0xffffffffu, val, off);
    if (l == 0) g_tp[e] = val * (1.0f / sqrtf(81920.0f));
}

// ---------------- bond MLP: k-loop unrolled by 4 with float4 ins loads ----------------
#define INS_STR 68
__global__ __launch_bounds__(512) void bond_kernel(float* __restrict__ out,
                                                   const float* __restrict__ ef,
                                                   const float* __restrict__ W1,
                                                   const float* __restrict__ b1,
                                                   const float* __restrict__ W2,
                                                   const float* __restrict__ b2) {
    extern __shared__ float sm[];
    float* W1s = sm;                    // [65 k][256 o]
    float* ins = W1s + 65 * 256;        // [64 e][68]: k 0..63 = ef, k=64 = tp
    float* W2s = ins + 64 * INS_STR;    // [5][257]
    float* b1s = W2s + 5 * 257;         // 256
    float* b2s = b1s + 256;             // 8
    const int t = threadIdx.x;
    const int e0 = blockIdx.x * 64;

    for (int idx = t; idx < 65 * 256; idx += 512) {
        int o = idx / 65, kk = idx % 65;
        int k = (kk == 0) ? 64 : (kk - 1);
        W1s[k * 256 + o] = W1[idx];
    }
#pragma unroll
    for (int q = 0; q < 2; q++) {
        int fidx = t + 512 * q;
        int e = fidx >> 4, k4 = (fidx & 15) * 4;
        float4 v = *(const float4*)&ef[(size_t)(e0 + e) * 64 + k4];
        *(float4*)&ins[e * INS_STR + k4] = v;
    }
    if (t < 64) ins[t * INS_STR + 64] = g_tp[e0 + t];
    if (t < 256) b1s[t] = b1[t];
    for (int idx = t; idx < 1280; idx += 512) {
        int j = idx >> 8, o = idx & 255;
        W2s[j * 257 + o] = W2[idx];
    }
    if (t < 5) b2s[t] = b2[t];
    __syncthreads();

    const int m = t & 31;
    const int el = (t >> 5) * 4;
    u64 acc[4][4];
#pragma unroll
    for (int p = 0; p < 4; p++)
#pragma unroll
        for (int b = 0; b < 4; b++) acc[p][b] = 0ull;

    const u64* W164 = (const u64*)W1s;
    // main k loop: 16 groups of 4 k's; ins loaded as one float4 per edge per group
#pragma unroll 2
    for (int kg = 0; kg < 64; kg += 4) {
        float4 iv0 = *(const float4*)&ins[(el + 0) * INS_STR + kg];
        float4 iv1 = *(const float4*)&ins[(el + 1) * INS_STR + kg];
        float4 iv2 = *(const float4*)&ins[(el + 2) * INS_STR + kg];
        float4 iv3 = *(const float4*)&ins[(el + 3) * INS_STR + kg];
        const float* f0 = (const float*)&iv0;
        const float* f1 = (const float*)&iv1;
        const float* f2 = (const float*)&iv2;
        const float* f3 = (const float*)&iv3;
#pragma unroll
        for (int kk = 0; kk < 4; kk++) {
            int k = kg + kk;
            u64 w0 = W164[k * 128 + m];
            u64 w1 = W164[k * 128 + 32 + m];
            u64 w2 = W164[k * 128 + 64 + m];
            u64 w3 = W164[k * 128 + 96 + m];
            u64 i0 = pk2(f0[kk], f0[kk]), i1 = pk2(f1[kk], f1[kk]);
            u64 i2 = pk2(f2[kk], f2[kk]), i3 = pk2(f3[kk], f3[kk]);
            fma2(acc[0][0], i0, w0); fma2(acc[0][1], i1, w0);
            fma2(acc[0][2], i2, w0); fma2(acc[0][3], i3, w0);
            fma2(acc[1][0], i0, w1); fma2(acc[1][1], i1, w1);
            fma2(acc[1][2], i2, w1); fma2(acc[1][3], i3, w1);
            fma2(acc[2][0], i0, w2); fma2(acc[2][1], i1, w2);
            fma2(acc[2][2], i2, w2); fma2(acc[2][3], i3, w2);
            fma2(acc[3][0], i0, w3); fma2(acc[3][1], i1, w3);
            fma2(acc[3][2], i2, w3); fma2(acc[3][3], i3, w3);
        }
    }
    // tail k = 64 (the tp input)
    {
        const int k = 64;
        u64 w0 = W164[k * 128 + m];
        u64 w1 = W164[k * 128 + 32 + m];
        u64 w2 = W164[k * 128 + 64 + m];
        u64 w3 = W164[k * 128 + 96 + m];
        float i0f = ins[(el + 0) * INS_STR + 64];
        float i1f = ins[(el + 1) * INS_STR + 64];
        float i2f = ins[(el + 2) * INS_STR + 64];
        float i3f = ins[(el + 3) * INS_STR + 64];
        u64 i0 = pk2(i0f, i0f), i1 = pk2(i1f, i1f);
        u64 i2 = pk2(i2f, i2f), i3 = pk2(i3f, i3f);
        fma2(acc[0][0], i0, w0); fma2(acc[0][1], i1, w0);
        fma2(acc[0][2], i2, w0); fma2(acc[0][3], i3, w0);
        fma2(acc[1][0], i0, w1); fma2(acc[1][1], i1, w1);
        fma2(acc[1][2], i2, w1); fma2(acc[1][3], i3, w1);
        fma2(acc[2][0], i0, w2); fma2(acc[2][1], i1, w2);
        fma2(acc[2][2], i2, w2); fma2(acc[2][3], i3, w2);
        fma2(acc[3][0], i0, w3); fma2(acc[3][1], i1, w3);
        fma2(acc[3][2], i2, w3); fma2(acc[3][3], i3, w3);
    }

    float hsl[8][4];
#pragma unroll
    for (int p = 0; p < 4; p++) {
        int ob = p * 64 + 2 * m;
        float bb0 = b1s[ob], bb1 = b1s[ob + 1];
#pragma unroll
        for (int b = 0; b < 4; b++) {
            float2 v = up2(acc[p][b]);
            float x0 = v.x + bb0, x1 = v.y + bb1;
            hsl[p * 2 + 0][b] = x0 / (1.f + __expf(-x0));
            hsl[p * 2 + 1][b] = x1 / (1.f + __expf(-x1));
        }
    }

    float p5[5][4];
#pragma unroll
    for (int j = 0; j < 5; j++) {
        float w2v[8];
#pragma unroll
        for (int a = 0; a < 8; a++) {
            int o = (a >> 1) * 64 + 2 * m + (a & 1);
            w2v[a] = W2s[j * 257 + o];
        }
#pragma unroll
        for (int b = 0; b < 4; b++) {
            float s = 0.f;
#pragma unroll
            for (int a = 0; a < 8; a++) s = fmaf(hsl[a][b], w2v[a], s);
            p5[j][b] = s;
        }
    }
#pragma unroll
    for (int j = 0; j < 5; j++)
#pragma unroll
        for (int b = 0; b < 4; b++) {
            float v = p5[j][b];
#pragma unroll
            for (int off = 16; off; off >>= 1) v += __shfl_xor_sync(0xffffffffu, v, off);
            p5[j][b] = v;
        }
    if (m < 20) {
        int b = m / 5, j = m % 5;
        float val = 0.f;
#pragma unroll
        for (int jj = 0; jj < 5; jj++)
#pragma unroll
            for (int bb2 = 0; bb2 < 4; bb2++)
                if (jj == j && bb2 == b) val = p5[jj][bb2];
        out[(size_t)(e0 + el + b) * 5 + j] = val + b2s[j];
    }
}

// ---------------- launch: R10-proven schedule (single chain + atom fork) ----------------
extern "C" void kernel_launch(void* const* d_in, const int* in_sizes, int n_in,
                              void* d_out, int out_size) {
    const float* h_final = (const float*)d_in[0];
    const float* e_final = (const float*)d_in[1];
    const int* edge_index = (const int*)d_in[4];
    const float* Ws_w = (const float*)d_in[5];
    const float* Ws_b = (const float*)d_in[6];
    const float* Wv = (const float*)d_in[7];
    const float* Wcoord = (const float*)d_in[8];
    const float* W_tp00 = (const float*)d_in[9];
    const float* W_tp11 = (const float*)d_in[10];
    const float* atom_W1 = (const float*)d_in[11];
    const float* atom_b1 = (const float*)d_in[12];
    const float* atom_W2 = (const float*)d_in[13];
    const float* atom_b2 = (const float*)d_in[14];
    const float* bond_W1 = (const float*)d_in[15];
    const float* bond_b1 = (const float*)d_in[16];
    const float* bond_W2 = (const float*)d_in[17];
    const float* bond_b2 = (const float*)d_in[18];

    float* out = (float*)d_out;
    float* out_atom = out;
    float* out_r0 = out + (size_t)N_NODES * 16;
    float* out_bond = out + (size_t)N_NODES * 16 + (size_t)N_NODES * 3;

    const int ZV_SMEM = (128 * ZV_RST + 32 * ZV_BST + 128) * 4;
    const int BD_SMEM = (65 * 256 + 64 * INS_STR + 5 * 257 + 256 + 8) * 4;
    const int AT_SMEM = (AT_N * 258 + 16 * 258 + 16) * 4;
    cudaFuncSetAttribute(zv_kernel, cudaFuncAttributeMaxDynamicSharedMemorySize, ZV_SMEM);
    cudaFuncSetAttribute(bond_kernel, cudaFuncAttributeMaxDynamicSharedMemorySize, BD_SMEM);
    cudaFuncSetAttribute(atom_kernel, cudaFuncAttributeMaxDynamicSharedMemorySize, AT_SMEM);

    cudaStream_t s1 = g_ar.s1;

    prep_kernel<<<257, 256>>>(atom_W1, Ws_w, Ws_b, atom_b1, Wcoord, Wv);
    node_gemm<<<dim3((N_NODES + 127) / 128, 4), 256>>>(h_final, W_tp00);
    cudaEventRecord(g_ar.eNG, 0);

    cudaStreamWaitEvent(s1, g_ar.eNG, 0);
    atom_kernel<<<(N_NODES + AT_N - 1) / AT_N, 256, AT_SMEM, s1>>>(out_atom, atom_W2, atom_b2);
    cudaEventRecord(g_ar.eA, s1);

    zv_kernel<<<dim3((N_NODES + ZVN - 1) / ZVN, 2), 256, ZV_SMEM>>>(h_final, W_tp11, out_r0);
    tp_kernel<<<N_EDGES / 8, 256>>>(edge_index);
    bond_kernel<<<N_EDGES / 64, 512, BD_SMEM>>>(out_bond, e_final, bond_W1, bond_b1,
                                                bond_W2, bond_b2);
    cudaStreamWaitEvent(0, g_ar.eA, 0);
}

// round 17
// speedup vs baseline: 1.1565x; 1.1565x over previous
#include <cuda_runtime.h>
#include <cuda_bf16.h>
#include <math.h>
#include <cstdint>

#define N_NODES 50000
#define N_EDGES 200000

typedef unsigned long long u64;

// ---- packed fp32x2 helpers ----
__device__ __forceinline__ u64 pk2(float x, float y) {
    u64 r; asm("mov.b64 %0,{%1,%2};" : "=l"(r) : "f"(x), "f"(y)); return r;
}
__device__ __forceinline__ void fma2(u64& d, u64 a, u64 b) {
    asm("fma.rn.f32x2 %0,%1,%2,%0;" : "+l"(d) : "l"(a), "l"(b));
}
__device__ __forceinline__ float2 up2(u64 v) {
    float2 r; asm("mov.b64 {%0,%1},%2;" : "=f"(r.x), "=f"(r.y) : "l"(v)); return r;
}
__device__ __forceinline__ unsigned pkbf(float lo, float hi) {
    unsigned r; asm("cvt.rn.bf16x2.f32 %0,%1,%2;" : "=r"(r) : "f"(hi), "f"(lo)); return r;
}
__device__ __forceinline__ float2 b22f(unsigned u) {
    __nv_bfloat162 h = *reinterpret_cast<__nv_bfloat162*>(&u);
    return __bfloat1622float2(h);
}

// ---------------- scratch ----------------
__device__ float g_M[256 * 256];
__device__ float g_bcomb[256];
__device__ float g_weff[128];
__device__ float g_hid[(size_t)N_NODES * 256];
__device__ __nv_bfloat16 g_ysb[(size_t)N_NODES * 256];
__device__ __nv_bfloat16 g_zvb[(size_t)N_NODES * 384];
__device__ __nv_bfloat16 g_hb[(size_t)N_NODES * 640];
__device__ float g_tp[N_EDGES];

// ---------------- stream/event resources ----------
struct AsyncRes {
    cudaStream_t s1;
    cudaEvent_t eFork, eY, eNG, eA;
    AsyncRes() {
        cudaStreamCreateWithFlags(&s1, cudaStreamNonBlocking);
        cudaEventCreateWithFlags(&eFork, cudaEventDisableTiming);
        cudaEventCreateWithFlags(&eY, cudaEventDisableTiming);
        cudaEventCreateWithFlags(&eNG, cudaEventDisableTiming);
        cudaEventCreateWithFlags(&eA, cudaEventDisableTiming);
    }
};
static AsyncRes g_ar;

// ---------------- prep ----------------
__global__ void prep_kernel(const float* __restrict__ A1, const float* __restrict__ Ws,
                            const float* __restrict__ Wsb, const float* __restrict__ ab1,
                            const float* __restrict__ Wcoord, const float* __restrict__ Wv) {
    if (blockIdx.x == 256) {
        int c = threadIdx.x;
        if (c < 128) {
            float acc = 0.f;
#pragma unroll 8
            for (int d = 0; d < 128; d++) acc = fmaf(Wcoord[d], Wv[d * 128 + c], acc);
            g_weff[c] = acc;
        }
        return;
    }
    __shared__ float a1s[256];
    int i = blockIdx.x, j = threadIdx.x;
    a1s[j] = A1[i * 256 + j];
    __syncthreads();
    float a[8];
#pragma unroll
    for (int u = 0; u < 8; u++) a[u] = 0.f;
#pragma unroll 4
    for (int k = 0; k < 256; k += 8) {
#pragma unroll
        for (int u = 0; u < 8; u++)
            a[u] = fmaf(a1s[k + u], Ws[(k + u) * 256 + j], a[u]);
    }
    g_M[i * 256 + j] = ((a[0] + a[1]) + (a[2] + a[3])) + ((a[4] + a[5]) + (a[6] + a[7]));
    if (j == 0) {
        float b = ab1[i];
        for (int k = 0; k < 256; k++) b = fmaf(a1s[k], Wsb[k], b);
        g_bcomb[i] = b;
    }
}

// ============================================================================
// ys via mma.sync bf16 HMMA: per CTA 128 nodes; ys[128,256] = xs[128,256] @ W^T
// A = xs (row-major M x K), B = W_tp00 (row-major N x K == col operand)
// 8 warps: wm = w&3 (m tile 32), wn = w>>2 (n tile 64 within 128-half)
// ============================================================================
#define YA_STR 264   // As row stride (256 + 8 pad), bf16
#define YB_STR 40    // Bs row stride (32 + 8 pad), bf16
#define YS_SMEM_BYTES (128 * YA_STR * 2 + 128 * YB_STR * 2)

__global__ __launch_bounds__(256) void ys_mma_kernel(const float* __restrict__ h,
                                                     const float* __restrict__ W) {
    extern __shared__ __nv_bfloat16 ysm[];
    __nv_bfloat16* As = ysm;                 // [128][264]
    __nv_bfloat16* Bs = ysm + 128 * YA_STR;  // [128][40]
    const int t = threadIdx.x;
    const int w = t >> 5, lane = t & 31;
    const int gid = lane >> 2, tig = lane & 3;
    const int wm = w & 3, wn = w >> 2;
    const int n0 = blockIdx.x * 128;
    const int m0 = wm * 32;

    // stage A: xs[128,256] fp32 -> bf16 (zero-fill rows >= N_NODES)
#pragma unroll
    for (int q = 0; q < 32; q++) {
        int u = t + 256 * q;                 // 8192 float4 units
        int row = u >> 6, c4 = (u & 63) * 4;
        float4 v = (n0 + row < N_NODES)
                       ? *(const float4*)&h[(size_t)(n0 + row) * 640 + c4]
                       : make_float4(0.f, 0.f, 0.f, 0.f);
        uint2 o = make_uint2(pkbf(v.x, v.y), pkbf(v.z, v.w));
        *(uint2*)&As[row * YA_STR + c4] = o;
    }

    for (int nt = 0; nt < 2; nt++) {
        float acc[2][8][4];
#pragma unroll
        for (int mf = 0; mf < 2; mf++)
#pragma unroll
            for (int nf = 0; nf < 8; nf++)
#pragma unroll
                for (int c = 0; c < 4; c++) acc[mf][nf][c] = 0.f;

        for (int kc = 0; kc < 8; kc++) {
            __syncthreads();
            // stage B chunk: W rows nt*128 .. +127, cols kc*32 .. +31
#pragma unroll
            for (int q = 0; q < 4; q++) {
                int u = t + 256 * q;         // 1024 float4 units
                int row = u >> 3, k4 = (u & 7) * 4;
                float4 v = *(const float4*)&W[(size_t)(nt * 128 + row) * 256 + kc * 32 + k4];
                uint2 o = make_uint2(pkbf(v.x, v.y), pkbf(v.z, v.w));
                *(uint2*)&Bs[row * YB_STR + k4] = o;
            }
            __syncthreads();

#pragma unroll
            for (int ks = 0; ks < 2; ks++) {
                const int kb = kc * 32 + ks * 16;   // global k base (As)
                const int kl = ks * 16;             // local k base (Bs)
                unsigned a[2][4];
#pragma unroll
                for (int mf = 0; mf < 2; mf++) {
                    int r0 = m0 + mf * 16 + gid;
                    a[mf][0] = *(const unsigned*)&As[r0 * YA_STR + kb + tig * 2];
                    a[mf][1] = *(const unsigned*)&As[(r0 + 8) * YA_STR + kb + tig * 2];
                    a[mf][2] = *(const unsigned*)&As[r0 * YA_STR + kb + 8 + tig * 2];
                    a[mf][3] = *(const unsigned*)&As[(r0 + 8) * YA_STR + kb + 8 + tig * 2];
                }
#pragma unroll
                for (int nf = 0; nf < 8; nf++) {
                    int nrow = wn * 64 + nf * 8 + gid;
                    unsigned b0 = *(const unsigned*)&Bs[nrow * YB_STR + kl + tig * 2];
                    unsigned b1 = *(const unsigned*)&Bs[nrow * YB_STR + kl + 8 + tig * 2];
#pragma unroll
                    for (int mf = 0; mf < 2; mf++) {
                        asm volatile(
                            "mma.sync.aligned.m16n8k16.row.col.f32.bf16.bf16.f32 "
                            "{%0,%1,%2,%3}, {%4,%5,%6,%7}, {%8,%9}, {%0,%1,%2,%3};"
                            : "+f"(acc[mf][nf][0]), "+f"(acc[mf][nf][1]),
                              "+f"(acc[mf][nf][2]), "+f"(acc[mf][nf][3])
                            : "r"(a[mf][0]), "r"(a[mf][1]), "r"(a[mf][2]), "r"(a[mf][3]),
                              "r"(b0), "r"(b1));
                    }
                }
            }
        }

        // epilogue: D[m][n] -> g_ysb bf16
#pragma unroll
        for (int mf = 0; mf < 2; mf++) {
            int mrow = n0 + m0 + mf * 16 + gid;
#pragma unroll
            for (int nf = 0; nf < 8; nf++) {
                int ncol = nt * 128 + wn * 64 + nf * 8 + tig * 2;
                if (mrow < N_NODES)
                    *(unsigned*)&g_ysb[(size_t)mrow * 256 + ncol] =
                        pkbf(acc[mf][nf][0], acc[mf][nf][1]);
                if (mrow + 8 < N_NODES)
                    *(unsigned*)&g_ysb[(size_t)(mrow + 8) * 256 + ncol] =
                        pkbf(acc[mf][nf][2], acc[mf][nf][3]);
            }
        }
    }
}

// ---------------- node GEMM: hid half only (by 0/1), R10-proven body ----------------
#define NG_STR 132
__global__ __launch_bounds__(256) void node_gemm(const float* __restrict__ h) {
    __shared__ float As[16 * NG_STR];
    __shared__ float Bs[16 * NG_STR];
    const int t = threadIdx.x;
    const int n0 = blockIdx.x * 128;
    const int by = blockIdx.y;                 // 0 or 1 (hid halves)
    const float* Bbase = g_M + (size_t)by * 128 * 256;
    const int lr = t >> 1;
    const int lk = (t & 1) * 8;
    const int ty = t >> 4, tx = t & 15;
    const int anode = n0 + lr;
    const bool aval = anode < N_NODES;
    const float* Aptr = h + (size_t)anode * 640 + lk;
    const float* Bptr = Bbase + (size_t)lr * 256 + lk;

    u64 acc[8][4];
#pragma unroll
    for (int m = 0; m < 8; m++)
#pragma unroll
        for (int q = 0; q < 4; q++) acc[m][q] = 0ull;

    float4 pa0, pa1, pb0, pb1;
    const float4 z4 = make_float4(0.f, 0.f, 0.f, 0.f);
    pa0 = aval ? *(const float4*)(Aptr + 0) : z4;
    pa1 = aval ? *(const float4*)(Aptr + 4) : z4;
    pb0 = *(const float4*)(Bptr + 0);
    pb1 = *(const float4*)(Bptr + 4);

    const u64* B64 = (const u64*)Bs;
    for (int k0 = 0; k0 < 256; k0 += 16) {
        if (by == 0 && aval) {
            uint4 o = make_uint4(pkbf(pa0.x, pa0.y), pkbf(pa0.z, pa0.w),
                                 pkbf(pa1.x, pa1.y), pkbf(pa1.z, pa1.w));
            *(uint4*)&g_hb[(size_t)anode * 640 + k0 + lk] = o;
        }
        As[(lk + 0) * NG_STR + lr] = pa0.x;
        As[(lk + 1) * NG_STR + lr] = pa0.y;
        As[(lk + 2) * NG_STR + lr] = pa0.z;
        As[(lk + 3) * NG_STR + lr] = pa0.w;
        As[(lk + 4) * NG_STR + lr] = pa1.x;
        As[(lk + 5) * NG_STR + lr] = pa1.y;
        As[(lk + 6) * NG_STR + lr] = pa1.z;
        As[(lk + 7) * NG_STR + lr] = pa1.w;
        Bs[(lk + 0) * NG_STR + lr] = pb0.x;
        Bs[(lk + 1) * NG_STR + lr] = pb0.y;
        Bs[(lk + 2) * NG_STR + lr] = pb0.z;
        Bs[(lk + 3) * NG_STR + lr] = pb0.w;
        Bs[(lk + 4) * NG_STR + lr] = pb1.x;
        Bs[(lk + 5) * NG_STR + lr] = pb1.y;
        Bs[(lk + 6) * NG_STR + lr] = pb1.z;
        Bs[(lk + 7) * NG_STR + lr] = pb1.w;
        __syncthreads();
        if (k0 + 16 < 256) {
            pa0 = aval ? *(const float4*)(Aptr + k0 + 16) : z4;
            pa1 = aval ? *(const float4*)(Aptr + k0 + 20) : z4;
            pb0 = *(const float4*)(Bptr + k0 + 16);
            pb1 = *(const float4*)(Bptr + k0 + 20);
        }
#pragma unroll
        for (int kk = 0; kk < 16; kk++) {
            float4 a0 = *(const float4*)&As[kk * NG_STR + ty * 8];
            float4 a1 = *(const float4*)&As[kk * NG_STR + ty * 8 + 4];
            u64 b0 = B64[kk * 66 + tx * 2];
            u64 b1 = B64[kk * 66 + tx * 2 + 1];
            u64 b2 = B64[kk * 66 + 32 + tx * 2];
            u64 b3 = B64[kk * 66 + 33 + tx * 2];
            float av[8] = {a0.x, a0.y, a0.z, a0.w, a1.x, a1.y, a1.z, a1.w};
#pragma unroll
            for (int m = 0; m < 8; m++) {
                u64 aa = pk2(av[m], av[m]);
                fma2(acc[m][0], aa, b0);
                fma2(acc[m][1], aa, b1);
                fma2(acc[m][2], aa, b2);
                fma2(acc[m][3], aa, b3);
            }
        }
        __syncthreads();
    }

    const int half = by * 128;
    const int j0 = half + tx * 4;
    const int j1 = half + 64 + tx * 4;
#pragma unroll
    for (int m = 0; m < 8; m++) {
        int node = n0 + ty * 8 + m;
        if (node >= N_NODES) continue;
        float2 v0 = up2(acc[m][0]), v1 = up2(acc[m][1]);
        float2 v2 = up2(acc[m][2]), v3 = up2(acc[m][3]);
        float4 bc0 = *(const float4*)&g_bcomb[j0];
        float4 bc1 = *(const float4*)&g_bcomb[j1];
        float x0 = v0.x + bc0.x, x1 = v0.y + bc0.y, x2 = v1.x + bc0.z, x3 = v1.y + bc0.w;
        float y0 = v2.x + bc1.x, y1 = v2.y + bc1.y, y2 = v3.x + bc1.z, y3 = v3.y + bc1.w;
        float4 o0 = make_float4(x0 / (1.f + __expf(-x0)), x1 / (1.f + __expf(-x1)),
                                x2 / (1.f + __expf(-x2)), x3 / (1.f + __expf(-x3)));
        float4 o1 = make_float4(y0 / (1.f + __expf(-y0)), y1 / (1.f + __expf(-y1)),
                                y2 / (1.f + __expf(-y2)), y3 / (1.f + __expf(-y3)));
        *(float4*)&g_hid[(size_t)node * 256 + j0] = o0;
        *(float4*)&g_hid[(size_t)node * 256 + j1] = o1;
    }
}

// ---------------- zv: c-split (R10-proven) ----------------
#define ZVN 32
#define ZV_RST 98
#define ZV_BST 66
#define ZT_STR 196
__global__ __launch_bounds__(256, 3) void zv_kernel(const float* __restrict__ h,
                                                    const float* __restrict__ Wtp11,
                                                    float* __restrict__ out_r0) {
    extern __shared__ float sm[];
    float* vsT = sm;
    float* Bs = sm + 128 * ZV_RST;
    float* weffs = Bs + 32 * ZV_BST;
    const int t = threadIdx.x;
    const int n0 = blockIdx.x * ZVN;
    const int c_base = blockIdx.y * 64;

#pragma unroll
    for (int q = 0; q < 12; q++) {
        int fidx = t + 256 * q;
        int n = fidx / 96, j4 = (fidx % 96) * 4;
        float4 v = (n0 + n < N_NODES)
                       ? *(const float4*)&h[(size_t)(n0 + n) * 640 + 256 + j4]
                       : make_float4(0.f, 0.f, 0.f, 0.f);
        if (blockIdx.y == 0 && n0 + n < N_NODES) {
            uint2 o = make_uint2(pkbf(v.x, v.y), pkbf(v.z, v.w));
            *(uint2*)&g_hb[(size_t)(n0 + n) * 640 + 256 + j4] = o;
        }
        float vv[4] = {v.x, v.y, v.z, v.w};
#pragma unroll
        for (int s = 0; s < 4; s++) {
            int j = j4 + s;
            vsT[(j / 3) * ZV_RST + n * 3 + (j % 3)] = vv[s];
        }
    }
    if (blockIdx.y == 0 && t < 128) weffs[t] = g_weff[t];
    __syncthreads();

    if (blockIdx.y == 0 && t < 96) {
        int n = t / 3, i = t % 3;
        if (n0 + n < N_NODES) {
            float acc = 0.f;
#pragma unroll 8
            for (int d = 0; d < 128; d++) acc = fmaf(vsT[d * ZV_RST + t], weffs[d], acc);
            out_r0[(size_t)(n0 + n) * 3 + i] = acc;
        }
    }

    const int ty = t >> 4, tx = t & 15;
    u64 acc[6][2];
#pragma unroll
    for (int j = 0; j < 6; j++) { acc[j][0] = 0ull; acc[j][1] = 0ull; }

    const u64* B64 = (const u64*)Bs;
    const u64* V64 = (const u64*)vsT;
    for (int chn = 0; chn < 4; chn++) {
        if (chn) __syncthreads();
        int d0 = chn * 32;
#pragma unroll
        for (int q = 0; q < 2; q++) {
            int fidx = t + 256 * q;
            int cc = fidx >> 3, d4 = (fidx & 7) * 4;
            float4 w = *(const float4*)&Wtp11[(size_t)(c_base + cc) * 128 + d0 + d4];
            Bs[(d4 + 0) * ZV_BST + cc] = w.x;
            Bs[(d4 + 1) * ZV_BST + cc] = w.y;
            Bs[(d4 + 2) * ZV_BST + cc] = w.z;
            Bs[(d4 + 3) * ZV_BST + cc] = w.w;
        }
        __syncthreads();
#pragma unroll 4
        for (int dd = 0; dd < 32; dd++) {
            int d = d0 + dd;
            u64 a01 = V64[d * 49 + ty * 3];
            u64 a23 = V64[d * 49 + ty * 3 + 1];
            u64 a45 = V64[d * 49 + ty * 3 + 2];
            u64 b0 = B64[dd * 33 + tx * 2];
            u64 b1 = B64[dd * 33 + tx * 2 + 1];
            float2 f01 = up2(a01), f23 = up2(a23), f45 = up2(a45);
            float av[6] = {f01.x, f01.y, f23.x, f23.y, f45.x, f45.y};
#pragma unroll
            for (int j = 0; j < 6; j++) {
                u64 aa = pk2(av[j], av[j]);
                fma2(acc[j][0], aa, b0);
                fma2(acc[j][1], aa, b1);
            }
        }
    }

    __syncthreads();
    float* zt = vsT;
#pragma unroll
    for (int j = 0; j < 6; j++) {
        int r = ty * 6 + j;
        int n = r / 3, i = r % 3;
        float2 v0 = up2(acc[j][0]);
        float2 v1 = up2(acc[j][1]);
        int cp = tx * 4;
        zt[n * ZT_STR + (cp + 0) * 3 + i] = v0.x;
        zt[n * ZT_STR + (cp + 1) * 3 + i] = v0.y;
        zt[n * ZT_STR + (cp + 2) * 3 + i] = v1.x;
        zt[n * ZT_STR + (cp + 3) * 3 + i] = v1.y;
    }
    __syncthreads();
#pragma unroll
    for (int q = 0; q < 6; q++) {
        int fidx = t + 256 * q;
        int n = fidx / 48, w = fidx % 48;
        if (n0 + n < N_NODES) {
            float4 v = *(const float4*)&zt[n * ZT_STR + w * 4];
            uint2 o = make_uint2(pkbf(v.x, v.y), pkbf(v.z, v.w));
            *(uint2*)&g_zvb[(size_t)(n0 + n) * 384 + c_base * 3 + w * 4] = o;
        }
    }
}

// ---------------- atom logits (R10-proven) ----------------
#define AT_N 64
__global__ __launch_bounds__(256) void atom_kernel(float* __restrict__ out,
                                                   const float* __restrict__ A2,
                                                   const float* __restrict__ b2) {
    extern __shared__ float sma[];
    float* hs = sma;
    float* a2s = hs + AT_N * 258;
    float* b2s = a2s + 16 * 258;
    const int t = threadIdx.x;
    const int n0 = blockIdx.x * AT_N;

#pragma unroll
    for (int q = 0; q < 32; q++) {
        int idx = t + 256 * q;
        int n = idx >> 7, k2 = (idx & 127) * 2;
        float2 v = (n0 + n < N_NODES)
                       ? *(const float2*)&g_hid[(size_t)(n0 + n) * 256 + k2]
                       : make_float2(0.f, 0.f);
        *(float2*)&hs[n * 258 + k2] = v;
    }
#pragma unroll
    for (int q = 0; q < 8; q++) {
        int idx = t + 256 * q;
        int j = idx >> 7, k2 = (idx & 127) * 2;
        *(float2*)&a2s[j * 258 + k2] = *(const float2*)&A2[j * 256 + k2];
    }
    if (t < 16) b2s[t] = b2[t];
    __syncthreads();

    const int jp = t & 7;
    const int np = t >> 3;
    const u64* H0 = (const u64*)hs + (2 * np) * 129;
    const u64* H1 = H0 + 129;
    const u64* A0 = (const u64*)a2s + (2 * jp) * 129;
    const u64* A1 = A0 + 129;
    u64 c00 = 0ull, c01 = 0ull, c10 = 0ull, c11 = 0ull;
#pragma unroll 8
    for (int kk = 0; kk < 128; kk++) {
        u64 h0 = H0[kk], h1 = H1[kk];
        u64 a0 = A0[kk], a1 = A1[kk];
        fma2(c00, h0, a0);
        fma2(c01, h0, a1);
        fma2(c10, h1, a0);
        fma2(c11, h1, a1);
    }
    float2 r00 = up2(c00), r01 = up2(c01), r10 = up2(c10), r11 = up2(c11);
    int n = n0 + 2 * np, j = 2 * jp;
    float bj0 = b2s[j], bj1 = b2s[j + 1];
    if (n < N_NODES) {
        *(float2*)&out[(size_t)n * 16 + j] =
            make_float2(r00.x + r00.y + bj0, r01.x + r01.y + bj1);
    }
    if (n + 1 < N_NODES) {
        *(float2*)&out[(size_t)(n + 1) * 16 + j] =
            make_float2(r10.x + r10.y + bj0, r11.x + r11.y + bj1);
    }
}

// ---------------- tp (R10-proven) ----------------
__global__ __launch_bounds__(256) void tp_kernel(const int* __restrict__ ei) {
    const int w = threadIdx.x >> 5, l = threadIdx.x & 31;
    const int e = blockIdx.x * 8 + w;
    const int row = ei[e];
    const int col = ei[N_EDGES + e];
    const __nv_bfloat16* hb = g_hb + (size_t)row * 640;
    const uint4* ys4 = (const uint4*)(g_ysb + (size_t)col * 256);
    const uint2* zv2 = (const uint2*)(g_zvb + (size_t)col * 384);
    const uint2* hv2 = (const uint2*)(hb + 256);

    uint4 x = *(const uint4*)(hb + 8 * l);
    uint4 y = ys4[l];
    float2 xa = b22f(x.x), xb = b22f(x.y), xc = b22f(x.z), xd = b22f(x.w);
    float2 ya = b22f(y.x), yb = b22f(y.y), yc = b22f(y.z), yd = b22f(y.w);
    float ss = xa.x * ya.x + xa.y * ya.y + xb.x * yb.x + xb.y * yb.y +
               xc.x * yc.x + xc.y * yc.y + xd.x * yd.x + xd.y * yd.y;

    float vv = 0.f;
#pragma unroll
    for (int q = 0; q < 3; q++) {
        uint2 xv = hv2[3 * l + q];
        uint2 z = zv2[3 * l + q];
        float2 x0 = b22f(xv.x), x1 = b22f(xv.y);
        float2 z0 = b22f(z.x), z1 = b22f(z.y);
        vv = fmaf(x0.x, z0.x, vv);
        vv = fmaf(x0.y, z0.y, vv);
        vv = fmaf(x1.x, z1.x, vv);
        vv = fmaf(x1.y, z1.y, vv);
    }
    float val = fmaf(vv, 0.57735026919f, ss);
#pragma unroll
    for (int off = 16; off; off >>= 1) val += __shfl_xor_sync(0xffffffffu, val, off);
    if (l == 0) g_tp[e] = val * (1.0f / sqrtf(81920.0f));
}

// ---------------- bond MLP (R10-proven) ----------------
#define INS_STR 68
__global__ __launch_bounds__(512) void bond_kernel(float* __restrict__ out,
                                                   const float* __restrict__ ef,
                                                   const float* __restrict__ W1,
                                                   const float* __restrict__ b1,
                                                   const float* __restrict__ W2,
                                                   const float* __restrict__ b2) {
    extern __shared__ float sm[];
    float* W1s = sm;
    float* ins = W1s + 65 * 256;
    float* W2s = ins + 64 * INS_STR;
    float* b1s = W2s + 5 * 257;
    float* b2s = b1s + 256;
    const int t = threadIdx.x;
    const int e0 = blockIdx.x * 64;

    for (int idx = t; idx < 65 * 256; idx += 512) {
        int o = idx / 65, kk = idx % 65;
        int k = (kk == 0) ? 64 : (kk - 1);
        W1s[k * 256 + o] = W1[idx];
    }
#pragma unroll
    for (int q = 0; q < 2; q++) {
        int fidx = t + 512 * q;
        int e = fidx >> 4, k4 = (fidx & 15) * 4;
        float4 v = *(const float4*)&ef[(size_t)(e0 + e) * 64 + k4];
        *(float4*)&ins[e * INS_STR + k4] = v;
    }
    if (t < 64) ins[t * INS_STR + 64] = g_tp[e0 + t];
    if (t < 256) b1s[t] = b1[t];
    for (int idx = t; idx < 1280; idx += 512) {
        int j = idx >> 8, o = idx & 255;
        W2s[j * 257 + o] = W2[idx];
    }
    if (t < 5) b2s[t] = b2[t];
    __syncthreads();

    const int m = t & 31;
    const int el = (t >> 5) * 4;
    u64 acc[4][4];
#pragma unroll
    for (int p = 0; p < 4; p++)
#pragma unroll
        for (int b = 0; b < 4; b++) acc[p][b] = 0ull;

    const u64* W164 = (const u64*)W1s;
#pragma unroll 5
    for (int k = 0; k < 65; k++) {
        u64 w0 = W164[k * 128 + m];
        u64 w1 = W164[k * 128 + 32 + m];
        u64 w2 = W164[k * 128 + 64 + m];
        u64 w3 = W164[k * 128 + 96 + m];
        float i0f = ins[(el + 0) * INS_STR + k];
        float i1f = ins[(el + 1) * INS_STR + k];
        float i2f = ins[(el + 2) * INS_STR + k];
        float i3f = ins[(el + 3) * INS_STR + k];
        u64 i0 = pk2(i0f, i0f), i1 = pk2(i1f, i1f);
        u64 i2 = pk2(i2f, i2f), i3 = pk2(i3f, i3f);
        fma2(acc[0][0], i0, w0); fma2(acc[0][1], i1, w0);
        fma2(acc[0][2], i2, w0); fma2(acc[0][3], i3, w0);
        fma2(acc[1][0], i0, w1); fma2(acc[1][1], i1, w1);
        fma2(acc[1][2], i2, w1); fma2(acc[1][3], i3, w1);
        fma2(acc[2][0], i0, w2); fma2(acc[2][1], i1, w2);
        fma2(acc[2][2], i2, w2); fma2(acc[2][3], i3, w2);
        fma2(acc[3][0], i0, w3); fma2(acc[3][1], i1, w3);
        fma2(acc[3][2], i2, w3); fma2(acc[3][3], i3, w3);
    }

    float hsl[8][4];
#pragma unroll
    for (int p = 0; p < 4; p++) {
        int ob = p * 64 + 2 * m;
        float bb0 = b1s[ob], bb1 = b1s[ob + 1];
#pragma unroll
        for (int b = 0; b < 4; b++) {
            float2 v = up2(acc[p][b]);
            float x0 = v.x + bb0, x1 = v.y + bb1;
            hsl[p * 2 + 0][b] = x0 / (1.f + __expf(-x0));
            hsl[p * 2 + 1][b] = x1 / (1.f + __expf(-x1));
        }
    }

    float p5[5][4];
#pragma unroll
    for (int j = 0; j < 5; j++) {
        float w2v[8];
#pragma unroll
        for (int a = 0; a < 8; a++) {
            int o = (a >> 1) * 64 + 2 * m + (a & 1);
            w2v[a] = W2s[j * 257 + o];
        }
#pragma unroll
        for (int b = 0; b < 4; b++) {
            float s = 0.f;
#pragma unroll
            for (int a = 0; a < 8; a++) s = fmaf(hsl[a][b], w2v[a], s);
            p5[j][b] = s;
        }
    }
#pragma unroll
    for (int j = 0; j < 5; j++)
#pragma unroll
        for (int b = 0; b < 4; b++) {
            float v = p5[j][b];
#pragma unroll
            for (int off = 16; off; off >>= 1) v += __shfl_xor_sync(0xffffffffu, v, off);
            p5[j][b] = v;
        }
    if (m < 20) {
        int b = m / 5, j = m % 5;
        float val = 0.f;
#pragma unroll
        for (int jj = 0; jj < 5; jj++)
#pragma unroll
            for (int bb2 = 0; bb2 < 4; bb2++)
                if (jj == j && bb2 == b) val = p5[jj][bb2];
        out[(size_t)(e0 + el + b) * 5 + j] = val + b2s[j];
    }
}

// ---------------- launch ----------------
extern "C" void kernel_launch(void* const* d_in, const int* in_sizes, int n_in,
                              void* d_out, int out_size) {
    const float* h_final = (const float*)d_in[0];
    const float* e_final = (const float*)d_in[1];
    const int* edge_index = (const int*)d_in[4];
    const float* Ws_w = (const float*)d_in[5];
    const float* Ws_b = (const float*)d_in[6];
    const float* Wv = (const float*)d_in[7];
    const float* Wcoord = (const float*)d_in[8];
    const float* W_tp00 = (const float*)d_in[9];
    const float* W_tp11 = (const float*)d_in[10];
    const float* atom_W1 = (const float*)d_in[11];
    const float* atom_b1 = (const float*)d_in[12];
    const float* atom_W2 = (const float*)d_in[13];
    const float* atom_b2 = (const float*)d_in[14];
    const float* bond_W1 = (const float*)d_in[15];
    const float* bond_b1 = (const float*)d_in[16];
    const float* bond_W2 = (const float*)d_in[17];
    const float* bond_b2 = (const float*)d_in[18];

    float* out = (float*)d_out;
    float* out_atom = out;
    float* out_r0 = out + (size_t)N_NODES * 16;
    float* out_bond = out + (size_t)N_NODES * 16 + (size_t)N_NODES * 3;

    const int ZV_SMEM = (128 * ZV_RST + 32 * ZV_BST + 128) * 4;
    const int BD_SMEM = (65 * 256 + 64 * INS_STR + 5 * 257 + 256 + 8) * 4;
    const int AT_SMEM = (AT_N * 258 + 16 * 258 + 16) * 4;
    cudaFuncSetAttribute(zv_kernel, cudaFuncAttributeMaxDynamicSharedMemorySize, ZV_SMEM);
    cudaFuncSetAttribute(bond_kernel, cudaFuncAttributeMaxDynamicSharedMemorySize, BD_SMEM);
    cudaFuncSetAttribute(atom_kernel, cudaFuncAttributeMaxDynamicSharedMemorySize, AT_SMEM);
    cudaFuncSetAttribute(ys_mma_kernel, cudaFuncAttributeMaxDynamicSharedMemorySize, YS_SMEM_BYTES);

    cudaStream_t s1 = g_ar.s1;
    const int NGX = (N_NODES + 127) / 128;

    // fork s1 from capture stream
    cudaEventRecord(g_ar.eFork, 0);
    cudaStreamWaitEvent(s1, g_ar.eFork, 0);

    // s1: ys via HMMA (no deps) — overlaps prep + hid node_gemm (fma-bound)
    ys_mma_kernel<<<NGX, 256, YS_SMEM_BYTES, s1>>>(h_final, W_tp00);
    cudaEventRecord(g_ar.eY, s1);

    // s0: prep -> node_gemm (hid only)
    prep_kernel<<<257, 256>>>(atom_W1, Ws_w, Ws_b, atom_b1, Wcoord, Wv);
    node_gemm<<<dim3(NGX, 2), 256>>>(h_final);
    cudaEventRecord(g_ar.eNG, 0);

    // s1: atom after node_gemm, overlaps zv/tp
    cudaStreamWaitEvent(s1, g_ar.eNG, 0);
    atom_kernel<<<(N_NODES + AT_N - 1) / AT_N, 256, AT_SMEM, s1>>>(out_atom, atom_W2, atom_b2);
    cudaEventRecord(g_ar.eA, s1);

    // s0: zv, then tp (needs ys from s1), bond
    zv_kernel<<<dim3((N_NODES + ZVN - 1) / ZVN, 2), 256, ZV_SMEM>>>(h_final, W_tp11, out_r0);
    cudaStreamWaitEvent(0, g_ar.eY, 0);
    tp_kernel<<<N_EDGES / 8, 256>>>(edge_index);
    bond_kernel<<<N_EDGES / 64, 512, BD_SMEM>>>(out_bond, e_final, bond_W1, bond_b1,
                                                bond_W2, bond_b2);
    cudaStreamWaitEvent(0, g_ar.eA, 0);
}